// round 3
// baseline (speedup 1.0000x reference)
#include <cuda_runtime.h>
#include <cuda_bf16.h>

#define N_ATOMS 50000
#define N_PAIRS 800000
#define X_DIM 3
#define N_PROP 64
#define N_ROWS (N_ATOMS * X_DIM)   // 150000

// Scratch: Y = px@wi, Z = px@wj, each [150000 x 64] f32 = 38.4 MB.
// Declared as float4 for guaranteed 16B alignment.
__device__ float4 g_Y[N_ROWS * (N_PROP / 4)];
__device__ float4 g_Z[N_ROWS * (N_PROP / 4)];

// ---------------------------------------------------------------------------
// Kernel 1: Y/Z precompute. C[150000 x 128] = px[150000 x 64] @ [wi | wj].
// Block tile 128 rows x 128 cols, 256 threads, 8x8 register tile, K chunked 32.
// ---------------------------------------------------------------------------
__global__ void __launch_bounds__(256) precompute_kernel(
    const float* __restrict__ px,
    const float* __restrict__ wi,
    const float* __restrict__ wj)
{
    __shared__ float s_px[32][129];   // [z][row_local], pad 129 (odd) -> conflict-free
    __shared__ float s_w [32][132];   // [z][g 0..127], pad 132 keeps 16B alignment

    const int tid  = threadIdx.x;
    const int row0 = blockIdx.x * 128;
    const int tx   = tid & 15;        // col group (8 cols each)
    const int ty   = tid >> 4;        // row group (8 rows each)

    float acc[8][8];
#pragma unroll
    for (int r = 0; r < 8; r++)
#pragma unroll
        for (int c = 0; c < 8; c++) acc[r][c] = 0.f;

    for (int kk = 0; kk < N_PROP; kk += 32) {
        // Load W chunk: 32 z x 128 g (cols 0-63 = wi, 64-127 = wj)
#pragma unroll
        for (int l = 0; l < 16; l++) {
            int idx = tid + l * 256;
            int z = idx >> 7, g = idx & 127;
            s_w[z][g] = (g < 64) ? wi[(kk + z) * 64 + g]
                                 : wj[(kk + z) * 64 + (g - 64)];
        }
        // Load px chunk transposed: 128 rows x 32 z
#pragma unroll
        for (int l = 0; l < 16; l++) {
            int idx = tid + l * 256;
            int r = idx >> 5, z = idx & 31;
            int row = row0 + r;
            s_px[z][r] = (row < N_ROWS) ? px[row * 64 + kk + z] : 0.f;
        }
        __syncthreads();

#pragma unroll 4
        for (int z = 0; z < 32; z++) {
            float a[8];
#pragma unroll
            for (int r = 0; r < 8; r++) a[r] = s_px[z][ty * 8 + r];
            float4 b0 = *(const float4*)&s_w[z][tx * 8];
            float4 b1 = *(const float4*)&s_w[z][tx * 8 + 4];
            float b[8] = {b0.x, b0.y, b0.z, b0.w, b1.x, b1.y, b1.z, b1.w};
#pragma unroll
            for (int r = 0; r < 8; r++)
#pragma unroll
                for (int c = 0; c < 8; c++)
                    acc[r][c] = fmaf(a[r], b[c], acc[r][c]);
        }
        __syncthreads();
    }

    // Store: cols 0-63 -> g_Y, cols 64-127 -> g_Z
    float* Yf = (float*)g_Y;
    float* Zf = (float*)g_Z;
    const int g0 = tx * 8;
#pragma unroll
    for (int r = 0; r < 8; r++) {
        int row = row0 + ty * 8 + r;
        if (row < N_ROWS) {
            float* dst = (g0 < 64) ? &Yf[row * 64 + g0]
                                   : &Zf[row * 64 + (g0 - 64)];
            float4 v0 = {acc[r][0], acc[r][1], acc[r][2], acc[r][3]};
            float4 v1 = {acc[r][4], acc[r][5], acc[r][6], acc[r][7]};
            *(float4*)dst       = v0;
            *(float4*)(dst + 4) = v1;
        }
    }
}

// ---------------------------------------------------------------------------
// Kernel 2: out[p] = Y[i_p] + Z[j_p], 48 float4 per pair (3 x 64 f32 = 192).
// 384 threads = 8 pairs x 48 float4 per block; addresses fully linear in tid
// so global stores/loads coalesce. __stcs on output to reduce L2 pollution.
// ---------------------------------------------------------------------------
__global__ void __launch_bounds__(384) gather_add_kernel(
    const int* __restrict__ ind,
    float4* __restrict__ out)
{
    const int tid = threadIdx.x;
    const int lp  = tid / 48;              // local pair 0..7
    const int t   = tid - lp * 48;         // element 0..47
    const int p   = blockIdx.x * 8 + lp;   // grid sized exactly: no guard

    const int i = __ldg(&ind[2 * p]);
    const int j = __ldg(&ind[2 * p + 1]);

    float4 a = __ldg(&g_Y[i * 48 + t]);
    float4 b = __ldg(&g_Z[j * 48 + t]);
    float4 r = {a.x + b.x, a.y + b.y, a.z + b.z, a.w + b.w};
    __stcs(&out[p * 48 + t], r);
}

// ---------------------------------------------------------------------------
extern "C" void kernel_launch(void* const* d_in, const int* in_sizes, int n_in,
                              void* d_out, int out_size)
{
    const int*   ind = (const int*)  d_in[0];   // [800000, 2] int32
    const float* px  = (const float*)d_in[1];   // [50000, 3, 64]
    const float* wi  = (const float*)d_in[2];   // [64, 64]
    const float* wj  = (const float*)d_in[3];   // [64, 64]
    float4*      out = (float4*)d_out;          // [800000, 3, 64] f32

    (void)in_sizes; (void)n_in; (void)out_size;

    precompute_kernel<<<(N_ROWS + 127) / 128, 256>>>(px, wi, wj);
    gather_add_kernel<<<N_PAIRS / 8, 384>>>(ind, out);
}

// round 5
// speedup vs baseline: 1.1569x; 1.1569x over previous
#include <cuda_runtime.h>
#include <cuda_fp16.h>
#include <cuda_bf16.h>

#define N_ATOMS 50000
#define N_PAIRS 800000
#define X_DIM 3
#define N_PROP 64
#define N_ROWS (N_ATOMS * X_DIM)   // 150000

// Scratch: Y = px@wi, Z = px@wj as fp16, each [150000 x 64] = 19.2 MB.
// uint4 = 8 halves -> 8 uint4 per row.
__device__ uint4 g_Yh[N_ROWS * 8];
__device__ uint4 g_Zh[N_ROWS * 8];

// ---- packed f32x2 helpers (Blackwell FFMA2 path; ptxas won't auto-fuse) ----
__device__ __forceinline__ unsigned long long pack2(float lo, float hi) {
    unsigned long long r;
    asm("mov.b64 %0, {%1, %2};" : "=l"(r) : "f"(lo), "f"(hi));
    return r;
}
__device__ __forceinline__ void unpack2(unsigned long long v, float& lo, float& hi) {
    asm("mov.b64 {%0, %1}, %2;" : "=f"(lo), "=f"(hi) : "l"(v));
}
__device__ __forceinline__ void fma2(unsigned long long& d, unsigned long long a,
                                     unsigned long long b, unsigned long long c) {
    asm("fma.rn.f32x2 %0, %1, %2, %3;" : "=l"(d) : "l"(a), "l"(b), "l"(c));
}

// ---------------------------------------------------------------------------
// Kernel 1: C[150000 x 128] = px[150000 x 64] @ [wi | wj], output fp16.
// 128x128 block tile, 256 threads, 8x8 register tile via 8x4 packed f32x2 accs.
// ---------------------------------------------------------------------------
__global__ void __launch_bounds__(256) precompute_kernel(
    const float* __restrict__ px,
    const float* __restrict__ wi,
    const float* __restrict__ wj)
{
    __shared__ float s_px[32][129];   // [z][row_local], pad 129 -> conflict-free transpose
    __shared__ float s_w [32][132];   // [z][g], pad 132 keeps 8B/16B alignment

    const int tid  = threadIdx.x;
    const int row0 = blockIdx.x * 128;
    const int tx   = tid & 15;        // col group (8 cols)
    const int ty   = tid >> 4;        // row group (8 rows)

    unsigned long long acc[8][4];     // 8 rows x 4 packed col-pairs
#pragma unroll
    for (int r = 0; r < 8; r++)
#pragma unroll
        for (int c = 0; c < 4; c++) acc[r][c] = 0ull;

    for (int kk = 0; kk < N_PROP; kk += 32) {
#pragma unroll
        for (int l = 0; l < 16; l++) {
            int idx = tid + l * 256;
            int z = idx >> 7, g = idx & 127;
            s_w[z][g] = (g < 64) ? wi[(kk + z) * 64 + g]
                                 : wj[(kk + z) * 64 + (g - 64)];
        }
#pragma unroll
        for (int l = 0; l < 16; l++) {
            int idx = tid + l * 256;
            int r = idx >> 5, z = idx & 31;
            int row = row0 + r;
            s_px[z][r] = (row < N_ROWS) ? px[row * 64 + kk + z] : 0.f;
        }
        __syncthreads();

#pragma unroll 4
        for (int z = 0; z < 32; z++) {
            unsigned long long ap[8];
#pragma unroll
            for (int r = 0; r < 8; r++) {
                float a = s_px[z][ty * 8 + r];
                ap[r] = pack2(a, a);
            }
            unsigned long long bp[4];
#pragma unroll
            for (int c = 0; c < 4; c++) {
                float2 b2 = *(const float2*)&s_w[z][tx * 8 + c * 2];
                bp[c] = pack2(b2.x, b2.y);
            }
#pragma unroll
            for (int r = 0; r < 8; r++)
#pragma unroll
                for (int c = 0; c < 4; c++)
                    fma2(acc[r][c], ap[r], bp[c], acc[r][c]);
        }
        __syncthreads();
    }

    // Store fp16: cols 0-63 -> g_Yh, 64-127 -> g_Zh. 8 halves = one uint4 per row.
    const int g0 = tx * 8;
#pragma unroll
    for (int r = 0; r < 8; r++) {
        int row = row0 + ty * 8 + r;
        if (row < N_ROWS) {
            float f[8];
#pragma unroll
            for (int c = 0; c < 4; c++) unpack2(acc[r][c], f[2 * c], f[2 * c + 1]);
            __half2 h0 = __floats2half2_rn(f[0], f[1]);
            __half2 h1 = __floats2half2_rn(f[2], f[3]);
            __half2 h2 = __floats2half2_rn(f[4], f[5]);
            __half2 h3 = __floats2half2_rn(f[6], f[7]);
            uint4 v = { *(unsigned*)&h0, *(unsigned*)&h1,
                        *(unsigned*)&h2, *(unsigned*)&h3 };
            if (g0 < 64) g_Yh[row * 8 + (g0 >> 3)]        = v;
            else         g_Zh[row * 8 + ((g0 - 64) >> 3)] = v;
        }
    }
}

// ---------------------------------------------------------------------------
// Kernel 2: out[p] = Y[i_p] + Z[j_p].
// 48 threads/pair: each loads 4 halves (8B) from Y and Z, converts, writes
// one float4. All addresses linear in t -> fully coalesced.
// ---------------------------------------------------------------------------
__global__ void __launch_bounds__(384) gather_add_kernel(
    const int2* __restrict__ ind,
    float4* __restrict__ out)
{
    const int tid = threadIdx.x;
    const int lp  = tid / 48;              // local pair 0..7
    const int t   = tid - lp * 48;         // element 0..47
    const int p   = blockIdx.x * 8 + lp;   // grid sized exactly

    const int2 ij = __ldg(&ind[p]);

    const uint2* Y = (const uint2*)g_Yh;   // uint2 = 4 halves; 48 per atom
    const uint2* Z = (const uint2*)g_Zh;
    uint2 ya = __ldg(&Y[ij.x * 48 + t]);
    uint2 zb = __ldg(&Z[ij.y * 48 + t]);

    float2 y0 = __half22float2(*(const __half2*)&ya.x);
    float2 y1 = __half22float2(*(const __half2*)&ya.y);
    float2 z0 = __half22float2(*(const __half2*)&zb.x);
    float2 z1 = __half22float2(*(const __half2*)&zb.y);

    float4 r = { y0.x + z0.x, y0.y + z0.y, y1.x + z1.x, y1.y + z1.y };
    __stcs(&out[p * 48 + t], r);
}

// ---------------------------------------------------------------------------
extern "C" void kernel_launch(void* const* d_in, const int* in_sizes, int n_in,
                              void* d_out, int out_size)
{
    const int2*  ind = (const int2*) d_in[0];   // [800000, 2] int32
    const float* px  = (const float*)d_in[1];   // [50000, 3, 64]
    const float* wi  = (const float*)d_in[2];   // [64, 64]
    const float* wj  = (const float*)d_in[3];   // [64, 64]
    float4*      out = (float4*)d_out;          // [800000, 3, 64] f32

    (void)in_sizes; (void)n_in; (void)out_size;

    precompute_kernel<<<(N_ROWS + 127) / 128, 256>>>(px, wi, wj);
    gather_add_kernel<<<N_PAIRS / 8, 384>>>(ind, out);
}

// round 8
// speedup vs baseline: 1.6704x; 1.4438x over previous
#include <cuda_runtime.h>
#include <cuda_fp16.h>
#include <cuda_bf16.h>

#define N_ATOMS 50000
#define N_PAIRS 800000
#define X_DIM 3
#define N_PROP 64
#define N_ROWS (N_ATOMS * X_DIM)   // 150000

// Scratch: Y = px@wi, Z = px@wj as fp16, each [150000 x 64] = 19.2 MB.
__device__ uint4 g_Yh[N_ROWS * 8];
__device__ uint4 g_Zh[N_ROWS * 8];

// ---- packed f32x2 helpers (Blackwell FFMA2 path; ptxas won't auto-fuse) ----
__device__ __forceinline__ unsigned long long pack2(float lo, float hi) {
    unsigned long long r;
    asm("mov.b64 %0, {%1, %2};" : "=l"(r) : "f"(lo), "f"(hi));
    return r;
}
__device__ __forceinline__ void unpack2(unsigned long long v, float& lo, float& hi) {
    asm("mov.b64 {%0, %1}, %2;" : "=f"(lo), "=f"(hi) : "l"(v));
}
__device__ __forceinline__ void fma2(unsigned long long& d, unsigned long long a,
                                     unsigned long long b, unsigned long long c) {
    asm("fma.rn.f32x2 %0, %1, %2, %3;" : "=l"(d) : "l"(a), "l"(b), "l"(c));
}

// ---------------------------------------------------------------------------
// Kernel 1: C[150000 x 128] = px[150000 x 64] @ [wi | wj], output fp16.
// 128x128 block tile, 256 threads, 8x8 register tile via 8x4 packed f32x2 accs.
// ---------------------------------------------------------------------------
__global__ void __launch_bounds__(256) precompute_kernel(
    const float* __restrict__ px,
    const float* __restrict__ wi,
    const float* __restrict__ wj)
{
    __shared__ float s_px[32][129];   // [z][row_local], pad 129 -> conflict-free transpose
    __shared__ float s_w [32][132];   // [z][g], pad 132 keeps 8B/16B alignment

    const int tid  = threadIdx.x;
    const int row0 = blockIdx.x * 128;
    const int tx   = tid & 15;        // col group (8 cols)
    const int ty   = tid >> 4;        // row group (8 rows)

    unsigned long long acc[8][4];     // 8 rows x 4 packed col-pairs
#pragma unroll
    for (int r = 0; r < 8; r++)
#pragma unroll
        for (int c = 0; c < 4; c++) acc[r][c] = 0ull;

    for (int kk = 0; kk < N_PROP; kk += 32) {
#pragma unroll
        for (int l = 0; l < 16; l++) {
            int idx = tid + l * 256;
            int z = idx >> 7, g = idx & 127;
            s_w[z][g] = (g < 64) ? wi[(kk + z) * 64 + g]
                                 : wj[(kk + z) * 64 + (g - 64)];
        }
#pragma unroll
        for (int l = 0; l < 16; l++) {
            int idx = tid + l * 256;
            int r = idx >> 5, z = idx & 31;
            int row = row0 + r;
            s_px[z][r] = (row < N_ROWS) ? px[row * 64 + kk + z] : 0.f;
        }
        __syncthreads();

#pragma unroll 4
        for (int z = 0; z < 32; z++) {
            unsigned long long ap[8];
#pragma unroll
            for (int r = 0; r < 8; r++) {
                float a = s_px[z][ty * 8 + r];
                ap[r] = pack2(a, a);
            }
            unsigned long long bp[4];
#pragma unroll
            for (int c = 0; c < 4; c++) {
                float2 b2 = *(const float2*)&s_w[z][tx * 8 + c * 2];
                bp[c] = pack2(b2.x, b2.y);
            }
#pragma unroll
            for (int r = 0; r < 8; r++)
#pragma unroll
                for (int c = 0; c < 4; c++)
                    fma2(acc[r][c], ap[r], bp[c], acc[r][c]);
        }
        __syncthreads();
    }

    // Store fp16: cols 0-63 -> g_Yh, 64-127 -> g_Zh. 8 halves = one uint4 per row.
    const int g0 = tx * 8;
#pragma unroll
    for (int r = 0; r < 8; r++) {
        int row = row0 + ty * 8 + r;
        if (row < N_ROWS) {
            float f[8];
#pragma unroll
            for (int c = 0; c < 4; c++) unpack2(acc[r][c], f[2 * c], f[2 * c + 1]);
            __half2 h0 = __floats2half2_rn(f[0], f[1]);
            __half2 h1 = __floats2half2_rn(f[2], f[3]);
            __half2 h2 = __floats2half2_rn(f[4], f[5]);
            __half2 h3 = __floats2half2_rn(f[6], f[7]);
            uint4 v = { *(unsigned*)&h0, *(unsigned*)&h1,
                        *(unsigned*)&h2, *(unsigned*)&h3 };
            if (g0 < 64) g_Yh[row * 8 + (g0 >> 3)]        = v;
            else         g_Zh[row * 8 + ((g0 - 64) >> 3)] = v;
        }
    }
}

// ---------------------------------------------------------------------------
// Kernel 2: out[p] = Y[i_p] + Z[j_p].
// Block = 384 threads = 8 pair-slots x 48 lanes; each thread handles 4 pairs
// (slots stride 8), so 32 pairs per block. Indices staged through shared
// (one coalesced 256B load), then all 8 gather loads issued back-to-back
// for MLP=8 before any conversion/add. All gather/store addresses linear
// in lane t -> fully coalesced.
// ---------------------------------------------------------------------------
__global__ void __launch_bounds__(384) gather_add_kernel(
    const int2* __restrict__ ind,
    float4* __restrict__ out)
{
    __shared__ int2 s_ij[32];

    const int tid  = threadIdx.x;
    const int base = blockIdx.x * 32;

    if (tid < 32) s_ij[tid] = __ldg(&ind[base + tid]);
    __syncthreads();

    const int lp = tid / 48;               // pair slot 0..7
    const int t  = tid - lp * 48;          // lane 0..47 (uint2 = 4 halves each)

    const uint2* Y = (const uint2*)g_Yh;   // 48 uint2 per atom-row
    const uint2* Z = (const uint2*)g_Zh;

    // Issue all 8 independent gather loads first (MLP=8).
    uint2 ya[4], zb[4];
#pragma unroll
    for (int k = 0; k < 4; k++) {
        int2 ij = s_ij[lp + 8 * k];        // broadcast within warp
        ya[k] = __ldg(&Y[ij.x * 48 + t]);
        zb[k] = __ldg(&Z[ij.y * 48 + t]);
    }

    // Convert, add, store.
#pragma unroll
    for (int k = 0; k < 4; k++) {
        float2 y0 = __half22float2(*(const __half2*)&ya[k].x);
        float2 y1 = __half22float2(*(const __half2*)&ya[k].y);
        float2 z0 = __half22float2(*(const __half2*)&zb[k].x);
        float2 z1 = __half22float2(*(const __half2*)&zb[k].y);
        float4 r = { y0.x + z0.x, y0.y + z0.y, y1.x + z1.x, y1.y + z1.y };
        const int p = base + lp + 8 * k;
        __stcs(&out[p * 48 + t], r);
    }
}

// ---------------------------------------------------------------------------
extern "C" void kernel_launch(void* const* d_in, const int* in_sizes, int n_in,
                              void* d_out, int out_size)
{
    const int2*  ind = (const int2*) d_in[0];   // [800000, 2] int32
    const float* px  = (const float*)d_in[1];   // [50000, 3, 64]
    const float* wi  = (const float*)d_in[2];   // [64, 64]
    const float* wj  = (const float*)d_in[3];   // [64, 64]
    float4*      out = (float4*)d_out;          // [800000, 3, 64] f32

    (void)in_sizes; (void)n_in; (void)out_size;

    precompute_kernel<<<(N_ROWS + 127) / 128, 256>>>(px, wi, wj);
    gather_add_kernel<<<N_PAIRS / 32, 384>>>(ind, out);
}